// round 2
// baseline (speedup 1.0000x reference)
#include <cuda_runtime.h>
#include <float.h>
#include <math.h>

#define BATCH 2
#define NSEQ  2048
#define DIM   1024
#define H     16
#define DH    64
#define NM    16
#define JTOT  2064          // NM + NSEQ
#define MROWS (BATCH*NSEQ)  // 4096

// ---------------- global scratch (static __device__, no allocations) ----------------
__device__ float g_Q[BATCH][H][NSEQ][DH];      // ~16.8 MB
__device__ float g_K[BATCH][H][JTOT][DH];      // ~16.9 MB (mem_k prepended)
__device__ float g_V[BATCH][H][JTOT][DH];      // ~16.9 MB
__device__ float g_dots[BATCH][H][NSEQ][JTOT]; // ~541 MB raw per-head dots
__device__ float g_ctx[BATCH][NSEQ][H*DH];     // ~16.8 MB attention output

// ---------------- fill mem_k / mem_v into K/V prefix ----------------
__global__ void memfill_kernel(const float* __restrict__ mk, const float* __restrict__ mv) {
    int idx = blockIdx.x * 256 + threadIdx.x;
    if (idx >= BATCH * H * NM * DH) return;
    int d = idx & 63;
    int j = (idx >> 6) & 15;
    int h = (idx >> 10) & 15;
    int b = idx >> 14;
    g_K[b][h][j][d] = mk[(h * NM + j) * DH + d];
    g_V[b][h][j][d] = mv[(h * NM + j) * DH + d];
}

// ---------------- QKV projection: x(4096x1024) @ W(1024x1024), 3 weights ----------------
__global__ __launch_bounds__(256) void gemm_qkv_kernel(
    const float* __restrict__ x, const float* __restrict__ Wq,
    const float* __restrict__ Wk, const float* __restrict__ Wv) {
    const int z = blockIdx.z;
    const float* W = (z == 0) ? Wq : (z == 1) ? Wk : Wv;
    __shared__ float As[32][68];  // As[k][m] (transposed)
    __shared__ float Bs[32][68];  // Bs[k][n]
    const int m0 = blockIdx.y << 6;
    const int n0 = blockIdx.x << 6;
    const int tid = threadIdx.x;
    const int ty = tid >> 4, tx = tid & 15;
    const int ar = tid >> 3, ac = (tid & 7) << 2;
    const int br = tid >> 4, bc = (tid & 15) << 2;
    float acc[4][4];
#pragma unroll
    for (int i = 0; i < 4; i++)
#pragma unroll
        for (int j = 0; j < 4; j++) acc[i][j] = 0.f;

    for (int k0 = 0; k0 < DIM; k0 += 32) {
        float4 a0 = *(const float4*)&x[(m0 + ar) * DIM + k0 + ac];
        float4 a1 = *(const float4*)&x[(m0 + ar + 32) * DIM + k0 + ac];
        float4 b0 = *(const float4*)&W[(k0 + br) * DIM + n0 + bc];
        float4 b1 = *(const float4*)&W[(k0 + br + 16) * DIM + n0 + bc];
        __syncthreads();
        As[ac + 0][ar] = a0.x; As[ac + 1][ar] = a0.y; As[ac + 2][ar] = a0.z; As[ac + 3][ar] = a0.w;
        As[ac + 0][ar + 32] = a1.x; As[ac + 1][ar + 32] = a1.y; As[ac + 2][ar + 32] = a1.z; As[ac + 3][ar + 32] = a1.w;
        *(float4*)&Bs[br][bc] = b0;
        *(float4*)&Bs[br + 16][bc] = b1;
        __syncthreads();
#pragma unroll
        for (int kk = 0; kk < 32; kk++) {
            float4 av = *(const float4*)&As[kk][ty << 2];
            float4 bv = *(const float4*)&Bs[kk][tx << 2];
            float a[4] = {av.x, av.y, av.z, av.w};
            float bb[4] = {bv.x, bv.y, bv.z, bv.w};
#pragma unroll
            for (int i = 0; i < 4; i++)
#pragma unroll
                for (int j = 0; j < 4; j++) acc[i][j] += a[i] * bb[j];
        }
    }
    // epilogue: scatter to head-major layout
#pragma unroll
    for (int i = 0; i < 4; i++) {
        int m = m0 + (ty << 2) + i;
        int b = m >> 11;
        int irow = m & 2047;
        int c = n0 + (tx << 2);
        int h = c >> 6;
        int d = c & 63;
        float4 v = make_float4(acc[i][0], acc[i][1], acc[i][2], acc[i][3]);
        if (z == 0)      *(float4*)&g_Q[b][h][irow][d] = v;
        else if (z == 1) *(float4*)&g_K[b][h][NM + irow][d] = v;
        else             *(float4*)&g_V[b][h][NM + irow][d] = v;
    }
}

// ---------------- raw dots: per (b,h), dots[i][j] = scale * Q[i]·K[j], causal tile-skip ----------------
__global__ __launch_bounds__(256) void dots_kernel() {
    const int bh = blockIdx.z;
    const int b = bh >> 4, h = bh & 15;
    const int i0 = blockIdx.y << 6;
    const int j0 = blockIdx.x << 6;
    if (j0 > i0 + 63 + NM) return;  // entire tile causally masked
    __shared__ float Qs[64][68];  // Qs[d][i]
    __shared__ float Ks[64][68];  // Ks[d][j]
    const int tid = threadIdx.x;
    const int ty = tid >> 4, tx = tid & 15;
    const int lr = tid >> 4;
    const int lc = (tid & 15) << 2;
#pragma unroll
    for (int rr = 0; rr < 64; rr += 16) {
        float4 q = *(const float4*)&g_Q[b][h][i0 + lr + rr][lc];
        Qs[lc + 0][lr + rr] = q.x; Qs[lc + 1][lr + rr] = q.y;
        Qs[lc + 2][lr + rr] = q.z; Qs[lc + 3][lr + rr] = q.w;
        int j = j0 + lr + rr;
        float4 kv = make_float4(0.f, 0.f, 0.f, 0.f);
        if (j < JTOT) kv = *(const float4*)&g_K[b][h][j][lc];
        Ks[lc + 0][lr + rr] = kv.x; Ks[lc + 1][lr + rr] = kv.y;
        Ks[lc + 2][lr + rr] = kv.z; Ks[lc + 3][lr + rr] = kv.w;
    }
    __syncthreads();
    float acc[4][4];
#pragma unroll
    for (int i = 0; i < 4; i++)
#pragma unroll
        for (int j = 0; j < 4; j++) acc[i][j] = 0.f;
#pragma unroll
    for (int kk = 0; kk < 64; kk++) {
        float4 av = *(const float4*)&Qs[kk][ty << 2];
        float4 bv = *(const float4*)&Ks[kk][tx << 2];
        float a[4] = {av.x, av.y, av.z, av.w};
        float bb[4] = {bv.x, bv.y, bv.z, bv.w};
#pragma unroll
        for (int i = 0; i < 4; i++)
#pragma unroll
            for (int j = 0; j < 4; j++) acc[i][j] += a[i] * bb[j];
    }
    const float scale = 0.125f;  // dh^-0.5
#pragma unroll
    for (int i = 0; i < 4; i++) {
        int irow = i0 + (ty << 2) + i;
        int jcol = j0 + (tx << 2);
        if (jcol < JTOT) {
            float4 v = make_float4(acc[i][0] * scale, acc[i][1] * scale,
                                   acc[i][2] * scale, acc[i][3] * scale);
            *(float4*)&g_dots[b][h][irow][jcol] = v;
        }
    }
}

// ---------------- fused per-row attention: premix, mask, top8, softmax, postmix, sparse AV ----------------
#define ATTN_SMEM_FLOATS (H*JTOT + 256 + 256 + 2048 + 16 + 256)
#define ATTN_SMEM_INTS   (JTOT + JTOT + 256)
#define ATTN_SMEM_BYTES  ((ATTN_SMEM_FLOATS + ATTN_SMEM_INTS) * 4)

__global__ __launch_bounds__(256) void attn_kernel(
    const float* __restrict__ pre, const float* __restrict__ post) {
    const int i = blockIdx.x;
    const int b = blockIdx.y;
    const int tid = threadIdx.x;
    extern __shared__ float sm[];
    float* s_d    = sm;                    // [16][2064] dots -> attn -> attn2
    float* s_pre  = s_d + H * JTOT;        // [16][16]
    float* s_post = s_pre + 256;           // [16][16]
    float* s_top  = s_post + 256;          // [16 rows][16 lists][8]
    float* s_sum  = s_top + 2048;          // [16]
    float* s_red  = s_sum + 16;            // [256]
    int* s_flag = (int*)(s_red + 256);     // [2064]
    int* s_list = s_flag + JTOT;           // [2064]
    int* s_scan = s_list + JTOT;           // [256]

    s_pre[tid]  = pre[tid];
    s_post[tid] = post[tid];
    const int nv = i + NM + 1;  // valid j: [0, nv)

    // load raw dots (valid range only)
    for (int h = 0; h < H; h++) {
        const float* src = &g_dots[b][h][i][0];
        float* dst = s_d + h * JTOT;
        for (int j = tid; j < nv; j += 256) dst[j] = src[j];
    }
    for (int j = tid; j < JTOT; j += 256) s_flag[j] = 0;
    __syncthreads();

    // premix across heads (in place per column) + causal mask
    for (int j = tid; j < JTOT; j += 256) {
        if (j < nv) {
            float r[16];
#pragma unroll
            for (int h2 = 0; h2 < 16; h2++) r[h2] = s_d[h2 * JTOT + j];
#pragma unroll
            for (int k = 0; k < 16; k++) {
                float a = 0.f;
#pragma unroll
                for (int h2 = 0; h2 < 16; h2++) a += r[h2] * s_pre[h2 * 16 + k];
                s_d[k * JTOT + j] = a;
            }
        } else {
#pragma unroll
            for (int k = 0; k < 16; k++) s_d[k * JTOT + j] = -FLT_MAX;
        }
    }
    __syncthreads();

    // ---- top-8 per row (16 threads per row) ----
    const int row = tid >> 4;
    const int t = tid & 15;
    const float* rd = s_d + row * JTOT;
    float t8[8];
#pragma unroll
    for (int q = 0; q < 8; q++) t8[q] = -FLT_MAX;
    for (int j = t; j < nv; j += 16) {
        float v = rd[j];
        if (v > t8[7]) {
            t8[7] = v;
#pragma unroll
            for (int q = 7; q >= 1; q--) {
                if (t8[q] > t8[q - 1]) { float tmp = t8[q]; t8[q] = t8[q - 1]; t8[q - 1] = tmp; }
            }
        }
    }
    {
        float* myl = s_top + (row * 16 + t) * 8;
#pragma unroll
        for (int q = 0; q < 8; q++) myl[q] = t8[q];
    }
    __syncthreads();
    // merge-tree: 16 sorted lists -> 1 (smem 2-pointer merges, deterministic)
#pragma unroll
    for (int L = 8; L >= 1; L >>= 1) {
        if (t < L) {
            float* A  = s_top + (row * 16 + t) * 8;
            float* B2 = s_top + (row * 16 + t + L) * 8;
            float out[8];
            int ia = 0, ib = 0;
#pragma unroll
            for (int r2 = 0; r2 < 8; r2++) {
                float va = A[ia];
                float vb = B2[ib];
                bool ta = (va >= vb);
                out[r2] = ta ? va : vb;
                ia += ta ? 1 : 0;
                ib += ta ? 0 : 1;
            }
#pragma unroll
            for (int r2 = 0; r2 < 8; r2++) A[r2] = out[r2];
        }
        __syncthreads();
    }
    const float thr = s_top[row * 128 + 7];
    const float mx  = s_top[row * 128 + 0];

    // ---- sum of exp over kept + set union flags ----
    float psum = 0.f;
    for (int j = t; j < nv; j += 16) {
        float v = rd[j];
        if (v >= thr) { psum += __expf(v - mx); s_flag[j] = 1; }
    }
    s_red[tid] = psum;
    __syncthreads();
    if (t == 0) {
        float s = 0.f;
#pragma unroll
        for (int q = 0; q < 16; q++) s += s_red[row * 16 + q];
        s_sum[row] = s;
    }
    __syncthreads();

    // ---- normalize (in place): attn values, zeros elsewhere ----
    {
        const float inv = 1.f / s_sum[row];
        float* wrow = s_d + row * JTOT;
        for (int j = t; j < nv; j += 16) {
            float v = wrow[j];
            wrow[j] = (v >= thr) ? __expf(v - mx) * inv : 0.f;
        }
    }
    __syncthreads();

    // ---- deterministic survivor compaction (chunk + prefix scan) ----
    const int CH = 9;  // 256*9 >= 2064
    int base = tid * CH;
    int end = base + CH; if (end > nv) end = nv;
    int c = 0;
    for (int j = base; j < end; j++) c += s_flag[j];
    s_scan[tid] = c;
    __syncthreads();
    for (int off = 1; off < 256; off <<= 1) {
        int v = s_scan[tid];
        int add = (tid >= off) ? s_scan[tid - off] : 0;
        __syncthreads();
        s_scan[tid] = v + add;
        __syncthreads();
    }
    {
        int pos = s_scan[tid] - c;
        for (int j = base; j < end; j++)
            if (s_flag[j]) s_list[pos++] = j;
    }
    __syncthreads();
    const int cnt = s_scan[255];

    // ---- post-mix at survivor columns only (in place) ----
    for (int sI = tid; sI < cnt; sI += 256) {
        int j = s_list[sI];
        float a[16];
#pragma unroll
        for (int h2 = 0; h2 < 16; h2++) a[h2] = s_d[h2 * JTOT + j];
#pragma unroll
        for (int k = 0; k < 16; k++) {
            float acc2 = 0.f;
#pragma unroll
            for (int h2 = 0; h2 < 16; h2++) acc2 += a[h2] * s_post[h2 * 16 + k];
            s_d[k * JTOT + j] = acc2;
        }
    }
    __syncthreads();

    // ---- sparse attn2 @ V: thread owns (k, 4 dims) ----
    const int kk2 = tid >> 4;
    const int d4 = (tid & 15) << 2;
    float ax = 0.f, ay = 0.f, az = 0.f, aw = 0.f;
    const float* Vb = &g_V[b][kk2][0][0];
    const float* wr = s_d + kk2 * JTOT;
    int s2 = 0;
    for (; s2 + 1 < cnt; s2 += 2) {
        int ja = s_list[s2], jb = s_list[s2 + 1];
        float wa = wr[ja], wb = wr[jb];
        float4 va = *(const float4*)(Vb + ja * 64 + d4);
        float4 vb = *(const float4*)(Vb + jb * 64 + d4);
        ax += wa * va.x + wb * vb.x;
        ay += wa * va.y + wb * vb.y;
        az += wa * va.z + wb * vb.z;
        aw += wa * va.w + wb * vb.w;
    }
    if (s2 < cnt) {
        int ja = s_list[s2];
        float wa = wr[ja];
        float4 va = *(const float4*)(Vb + ja * 64 + d4);
        ax += wa * va.x; ay += wa * va.y; az += wa * va.z; aw += wa * va.w;
    }
    float4 o = make_float4(ax, ay, az, aw);
    *(float4*)&g_ctx[b][i][kk2 * 64 + d4] = o;
}

// ---------------- output projection: ctx(4096x1024) @ Wo + bo ----------------
__global__ __launch_bounds__(256) void out_gemm_kernel(
    const float* __restrict__ Wo, const float* __restrict__ bo, float* __restrict__ out) {
    const float* A = &g_ctx[0][0][0];
    __shared__ float As[32][68];
    __shared__ float Bs[32][68];
    const int m0 = blockIdx.y << 6;
    const int n0 = blockIdx.x << 6;
    const int tid = threadIdx.x;
    const int ty = tid >> 4, tx = tid & 15;
    const int ar = tid >> 3, ac = (tid & 7) << 2;
    const int br = tid >> 4, bc = (tid & 15) << 2;
    float acc[4][4];
#pragma unroll
    for (int i = 0; i < 4; i++)
#pragma unroll
        for (int j = 0; j < 4; j++) acc[i][j] = 0.f;

    for (int k0 = 0; k0 < DIM; k0 += 32) {
        float4 a0 = *(const float4*)&A[(m0 + ar) * DIM + k0 + ac];
        float4 a1 = *(const float4*)&A[(m0 + ar + 32) * DIM + k0 + ac];
        float4 b0 = *(const float4*)&Wo[(k0 + br) * DIM + n0 + bc];
        float4 b1 = *(const float4*)&Wo[(k0 + br + 16) * DIM + n0 + bc];
        __syncthreads();
        As[ac + 0][ar] = a0.x; As[ac + 1][ar] = a0.y; As[ac + 2][ar] = a0.z; As[ac + 3][ar] = a0.w;
        As[ac + 0][ar + 32] = a1.x; As[ac + 1][ar + 32] = a1.y; As[ac + 2][ar + 32] = a1.z; As[ac + 3][ar + 32] = a1.w;
        *(float4*)&Bs[br][bc] = b0;
        *(float4*)&Bs[br + 16][bc] = b1;
        __syncthreads();
#pragma unroll
        for (int kk = 0; kk < 32; kk++) {
            float4 av = *(const float4*)&As[kk][ty << 2];
            float4 bv = *(const float4*)&Bs[kk][tx << 2];
            float a[4] = {av.x, av.y, av.z, av.w};
            float bb[4] = {bv.x, bv.y, bv.z, bv.w};
#pragma unroll
            for (int i = 0; i < 4; i++)
#pragma unroll
                for (int j = 0; j < 4; j++) acc[i][j] += a[i] * bb[j];
        }
    }
#pragma unroll
    for (int i = 0; i < 4; i++) {
        int m = m0 + (ty << 2) + i;
        int c = n0 + (tx << 2);
        float4 bias = *(const float4*)&bo[c];
        float4 v = make_float4(acc[i][0] + bias.x, acc[i][1] + bias.y,
                               acc[i][2] + bias.z, acc[i][3] + bias.w);
        *(float4*)&out[m * DIM + c] = v;
    }
}

// ---------------- launch ----------------
extern "C" void kernel_launch(void* const* d_in, const int* in_sizes, int n_in,
                              void* d_out, int out_size) {
    const float* x    = (const float*)d_in[0];
    const float* Wq   = (const float*)d_in[1];
    const float* Wk   = (const float*)d_in[2];
    const float* Wv   = (const float*)d_in[3];
    const float* pre  = (const float*)d_in[4];
    const float* post = (const float*)d_in[5];
    const float* mk   = (const float*)d_in[6];
    const float* mv   = (const float*)d_in[7];
    const float* Wo   = (const float*)d_in[8];
    const float* bo   = (const float*)d_in[9];
    float* out = (float*)d_out;

    cudaFuncSetAttribute(attn_kernel, cudaFuncAttributeMaxDynamicSharedMemorySize, ATTN_SMEM_BYTES);

    memfill_kernel<<<(BATCH * H * NM * DH + 255) / 256, 256>>>(mk, mv);
    gemm_qkv_kernel<<<dim3(DIM / 64, MROWS / 64, 3), 256>>>(x, Wq, Wk, Wv);
    dots_kernel<<<dim3((JTOT + 63) / 64, NSEQ / 64, BATCH * H), 256>>>();
    attn_kernel<<<dim3(NSEQ, BATCH), 256, ATTN_SMEM_BYTES>>>(pre, post);
    out_gemm_kernel<<<dim3(DIM / 64, MROWS / 64), 256>>>(Wo, bo, out);
}